// round 11
// baseline (speedup 1.0000x reference)
#include <cuda_runtime.h>
#include <cstdint>

// ============================================================================
// Problem constants
// ============================================================================
#define BATCH    4096
#define INPUTDIM 256
#define OUTDIM   256
#define GRIDSZ   64
#define KDIM     32768            // k = cs*16384 + i*64 + g
#define NPAIR    256              // loop over i; pair = (cos chunk i, sin chunk i)
#define MTILE    128
#define NTILE    64
#define MTILES   (BATCH / MTILE)  // 32
#define NTILES   (OUTDIM / NTILE) // 4
#define NTHREADS 384
#define NCONS    256              // consumer threads (warps 0-7: 4M x 2N)
#define NPROD    128              // producer threads (warps 8-11)

// SMEM stage (int8): 4 A buffers (cosHi,cosLo,sinHi,sinLo) 128 rows x 64B,
// 4 B buffers 64 rows x 64B; rows padded to 80 B:
//   - 80 % 16 == 0  -> uint4 STS / cp.async.16 aligned
//   - r*80 mod 128 covers all 8 16B-groups over 8 rows -> conflict-free LDSM
#define ROWB     80
#define ABUF     (128 * ROWB)     // 10240
#define BBUF     (64 * ROWB)      // 5120
#define OFF_B0   (4 * ABUF)       // 40960
#define STAGEB   (4 * ABUF + 4 * BBUF)   // 61440
#define NSTAGE   3
#define SM_BAR   (NSTAGE * STAGEB)       // 184320
#define SMEM_BYTES (SM_BAR + 64)

// Fixed-point scales: A = 2^13, B = 2^19; y = Shh*2^-18 + Smid*2^-25
#define HH_SCALE 3.814697265625e-6f       // 2^-18
#define MID_SCALE 2.98023223876953125e-8f // 2^-25

// ============================================================================
// Scratch (device globals — no allocation allowed)
// ============================================================================
__device__ int8_t g_Bh8[(size_t)OUTDIM * KDIM];   // B hi digit
__device__ int8_t g_Bl8[(size_t)OUTDIM * KDIM];   // B lo digit

// ============================================================================
// Helpers
// ============================================================================
__device__ __forceinline__ uint32_t smem_to_u32(const void* p) {
    uint32_t a;
    asm("{ .reg .u64 t; cvta.to.shared.u64 t, %1; cvt.u32.u64 %0, t; }"
        : "=r"(a) : "l"(p));
    return a;
}

__device__ __forceinline__ void cp_async16(uint32_t dst, const void* src) {
    asm volatile("cp.async.cg.shared.global [%0], [%1], 16;"
                 :: "r"(dst), "l"(src) : "memory");
}

__device__ __forceinline__ void ldsm_x4(uint32_t r[4], uint32_t addr) {
    asm volatile("ldmatrix.sync.aligned.m8n8.x4.shared.b16 {%0,%1,%2,%3}, [%4];"
                 : "=r"(r[0]), "=r"(r[1]), "=r"(r[2]), "=r"(r[3]) : "r"(addr));
}

// s8 MMA m16n8k32, int32 accumulate
__device__ __forceinline__ void imma16832(int acc[4], const uint32_t a[4],
                                          uint32_t b0, uint32_t b1) {
    asm volatile(
        "mma.sync.aligned.m16n8k32.row.col.s32.s8.s8.s32 "
        "{%0,%1,%2,%3}, {%4,%5,%6,%7}, {%8,%9}, {%0,%1,%2,%3};"
        : "+r"(acc[0]), "+r"(acc[1]), "+r"(acc[2]), "+r"(acc[3])
        : "r"(a[0]), "r"(a[1]), "r"(a[2]), "r"(a[3]), "r"(b0), "r"(b1));
}

#define MBAR_INIT(addr, cnt) \
    asm volatile("mbarrier.init.shared.b64 [%0], %1;" \
                 :: "r"((uint32_t)(addr)), "r"((uint32_t)(cnt)) : "memory")

#define MBAR_ARRIVE(addr) \
    asm volatile("mbarrier.arrive.shared.b64 _, [%0];" \
                 :: "r"((uint32_t)(addr)) : "memory")

#define MBAR_WAIT(addr, parity) do { \
    uint32_t _m = (uint32_t)(addr), _p = (uint32_t)(parity), _d; \
    asm volatile( \
        "{\n\t.reg .pred p;\n\t" \
        "mbarrier.try_wait.parity.acquire.cta.shared::cta.b64 p, [%1], %2;\n\t" \
        "selp.b32 %0, 1, 0, p;\n\t}" \
        : "=r"(_d) : "r"(_m), "r"(_p) : "memory"); \
    if (!_d) { \
        asm volatile( \
            "{\n\t.reg .pred P1;\n\t" \
            "WL_%=:\n\t" \
            "mbarrier.try_wait.parity.acquire.cta.shared::cta.b64 P1, [%0], %1, 0x989680;\n\t" \
            "@P1 bra.uni WD_%=;\n\t" \
            "bra.uni WL_%=;\n\t" \
            "WD_%=:\n\t}" \
            :: "r"(_m), "r"(_p) : "memory"); \
    } \
} while (0)

// ============================================================================
// Kernel 1: prep — fouriercoeffs f32 -> K-major int8 hi/lo digits (scale 2^19)
// ============================================================================
__global__ void prep_kernel(const float* __restrict__ cf) {
    size_t idx = (size_t)blockIdx.x * 256 + threadIdx.x;
    if (idx >= (size_t)OUTDIM * KDIM) return;
    int o = (int)(idx >> 15);            // KDIM = 2^15
    int k = (int)(idx & (KDIM - 1));
    int cs = k >> 14;
    int i  = (k >> 6) & (INPUTDIM - 1);
    int g  = k & (GRIDSZ - 1);
    float v = cf[(((size_t)cs * OUTDIM + o) * INPUTDIM + i) * GRIDSZ + g];
    int b19 = __float2int_rn(v * 524288.f);     // |b19| <= 7096
    int bh  = (b19 + 64) >> 7;                  // [-56, 56]
    int bl  = b19 - (bh << 7);                  // [-64, 63]
    g_Bh8[idx] = (int8_t)bh;
    g_Bl8[idx] = (int8_t)bl;
}

// ============================================================================
// Kernel 2: warp-specialized fused int8 GEMM
//   128 CTAs (32 M x 4 N), 384 threads:
//     warps 0-7  : consumers — warp (wm, wn): 32(M) x 32(N), cos+sin halves,
//                  dual int32 accumulators (HH weight 2^14, MID weight 2^7)
//     warps 8-11 : producers — thread=row, 64-step rotation at scale 2^13,
//                  digit split, packed int8 STS.128; B digits via cp.async
//   3-stage mbarrier ring; producer waits EVERY iteration with phase init 1
//   (first NSTAGE waits pass immediately) — fixes R10 parity deadlock.
// ============================================================================
__global__ void __launch_bounds__(NTHREADS, 1)
fourier_gemm(const float* __restrict__ x, const float* __restrict__ bias,
             float* __restrict__ out) {
    extern __shared__ char smem[];
    const uint32_t su32 = smem_to_u32(smem);
    const int tid = threadIdx.x;
    const int lid = tid & 31, wid = tid >> 5;
    const int mtile = blockIdx.x & (MTILES - 1);
    const int ntile = blockIdx.x >> 5;

    // barriers: full[0..2] at SM_BAR, empty[0..2] at SM_BAR+24
    const uint32_t barb = su32 + SM_BAR;
    if (tid == 0) {
        #pragma unroll
        for (int s = 0; s < NSTAGE; ++s) {
            MBAR_INIT(barb + s * 8,      NPROD);   // full
            MBAR_INIT(barb + 24 + s * 8, NCONS);   // empty
        }
    }
    __syncthreads();

    if (tid < NCONS) {
        // ==================== CONSUMER (warps 0-7) ====================
        const int wm = wid & 3;                   // M-row group (SMSP)
        const int wn = wid >> 2;                  // N 32-col group
        const int mat = lid >> 3, mr = lid & 7;
        // A frag: rows wm*32 + (mat&1)*8 + mr, k-bytes (mat>>1)*16
        const uint32_t a_off =
            (uint32_t)((wm * 32 + (mat & 1) * 8 + mr) * ROWB + (mat >> 1) * 16);
        // B frag: rows wn*32 + (mat>>1)*8 + mr, k-bytes (mat&1)*16
        const uint32_t b_off =
            (uint32_t)((wn * 32 + (mat >> 1) * 8 + mr) * ROWB + (mat & 1) * 16);

        int HH[2][4][4], MID[2][4][4];
        #pragma unroll
        for (int mt = 0; mt < 2; ++mt)
            #pragma unroll
            for (int nt = 0; nt < 4; ++nt)
                #pragma unroll
                for (int q = 0; q < 4; ++q) { HH[mt][nt][q] = 0; MID[mt][nt][q] = 0; }

        int s = 0, pf = 0;
        for (int it = 0; it < NPAIR; ++it) {
            MBAR_WAIT(barb + s * 8, pf);
            const uint32_t sbase = su32 + s * STAGEB;

            #pragma unroll
            for (int q = 0; q < 2; ++q) {          // q=0 cos, q=1 sin
                const uint32_t aHi = sbase + q * (2 * ABUF) + a_off;
                const uint32_t aLo = aHi + ABUF;
                const uint32_t bHi = sbase + OFF_B0 + q * (2 * BBUF) + b_off;
                const uint32_t bLo = bHi + BBUF;

                #pragma unroll
                for (int ks = 0; ks < 2; ++ks) {   // two K=32 steps per 64B row
                    const uint32_t ko = ks * 32;
                    uint32_t Ah[2][4], Al[2][4], Bh[2][4], Bl[2][4];
                    ldsm_x4(Ah[0], aHi + ko);
                    ldsm_x4(Ah[1], aHi + 16 * ROWB + ko);
                    ldsm_x4(Bh[0], bHi + ko);
                    ldsm_x4(Bh[1], bHi + 16 * ROWB + ko);
                    #pragma unroll
                    for (int mt = 0; mt < 2; ++mt)
                        #pragma unroll
                        for (int g = 0; g < 2; ++g) {
                            imma16832(HH[mt][g * 2],     Ah[mt], Bh[g][0], Bh[g][1]);
                            imma16832(HH[mt][g * 2 + 1], Ah[mt], Bh[g][2], Bh[g][3]);
                        }
                    ldsm_x4(Al[0], aLo + ko);
                    ldsm_x4(Al[1], aLo + 16 * ROWB + ko);
                    #pragma unroll
                    for (int mt = 0; mt < 2; ++mt)
                        #pragma unroll
                        for (int g = 0; g < 2; ++g) {
                            imma16832(MID[mt][g * 2],     Al[mt], Bh[g][0], Bh[g][1]);
                            imma16832(MID[mt][g * 2 + 1], Al[mt], Bh[g][2], Bh[g][3]);
                        }
                    ldsm_x4(Bl[0], bLo + ko);
                    ldsm_x4(Bl[1], bLo + 16 * ROWB + ko);
                    #pragma unroll
                    for (int mt = 0; mt < 2; ++mt)
                        #pragma unroll
                        for (int g = 0; g < 2; ++g) {
                            imma16832(MID[mt][g * 2],     Ah[mt], Bl[g][0], Bl[g][1]);
                            imma16832(MID[mt][g * 2 + 1], Ah[mt], Bl[g][2], Bl[g][3]);
                        }
                }
            }
            MBAR_ARRIVE(barb + 24 + s * 8);
            if (++s == NSTAGE) { s = 0; pf ^= 1; }
        }

        // ---- epilogue: distinct 32x32 tiles per warp, no smem needed ----
        #pragma unroll
        for (int mt = 0; mt < 2; ++mt) {
            int r0 = mtile * MTILE + wm * 32 + mt * 16 + (lid >> 2);
            #pragma unroll
            for (int nt = 0; nt < 4; ++nt) {
                int c0 = ntile * NTILE + wn * 32 + nt * 8 + (lid & 3) * 2;
                float b0 = __ldg(bias + c0);
                float b1 = __ldg(bias + c0 + 1);
                float y0 = (float)HH[mt][nt][0] * HH_SCALE
                         + (float)MID[mt][nt][0] * MID_SCALE + b0;
                float y1 = (float)HH[mt][nt][1] * HH_SCALE
                         + (float)MID[mt][nt][1] * MID_SCALE + b1;
                float y2 = (float)HH[mt][nt][2] * HH_SCALE
                         + (float)MID[mt][nt][2] * MID_SCALE + b0;
                float y3 = (float)HH[mt][nt][3] * HH_SCALE
                         + (float)MID[mt][nt][3] * MID_SCALE + b1;
                *(float2*)(out + (size_t)r0 * OUTDIM + c0) = make_float2(y0, y1);
                *(float2*)(out + (size_t)(r0 + 8) * OUTDIM + c0) = make_float2(y2, y3);
            }
        }
    } else {
        // ==================== PRODUCER (warps 8-11) ====================
        const int ptid = tid - NCONS;               // 0..127 == row
        const int fb = ptid;
        const float* xrow = x + (size_t)(mtile * MTILE + fb) * INPUTDIM;
        const int8_t* bhp = g_Bh8;
        const int8_t* blp = g_Bl8;

        // DEADLOCK FIX: wait every iteration, phase init 1 -> first NSTAGE
        // waits pass immediately (empty ring starts "full").
        int s = 0, pe = 1;
        for (int it = 0; it < NPAIR; ++it) {
            MBAR_WAIT(barb + 24 + s * 8, pe);
            const uint32_t sbase = su32 + s * STAGEB;

            // ---- B tiles: 4 buffers (cosH,cosL,sinH,sinL), 16 KB ----
            #pragma unroll
            for (int q = 0; q < 8; ++q) {
                int idx = ptid + q * NPROD;          // 0..1023 segs of 16B
                int buf = idx >> 8;                  // 0..3
                int r   = (idx >> 2) & 63;
                int seg = idx & 3;
                int cs  = buf >> 1;
                uint32_t dst = sbase + OFF_B0 + buf * BBUF + r * ROWB + seg * 16;
                const int8_t* src = ((buf & 1) ? blp : bhp)
                    + (size_t)(ntile * NTILE + r) * KDIM
                    + (size_t)cs * 16384 + (size_t)it * 64 + seg * 16;
                cp_async16(dst, src);
            }
            asm volatile("cp.async.commit_group;" ::: "memory");

            // ---- A: rotation at scale 2^13, digit split, packed STS.128 ----
            {
                float xv = __ldg(xrow + it);
                float S, C;
                sincosf(xv, &S, &C);
                float c0 = 8192.f * C, s0 = 8192.f * S;   // freq 1, scaled

                char* pch = smem + s * STAGEB + fb * ROWB;            // cos hi
                char* pcl = pch + ABUF;                               // cos lo
                char* psh = pch + 2 * ABUF;                           // sin hi
                char* psl = pch + 3 * ABUF;                           // sin lo

                #pragma unroll
                for (int w = 0; w < 4; ++w) {       // 4 x 16 g values
                    uint32_t wch[4], wcl[4], wsh[4], wsl[4];
                    #pragma unroll
                    for (int p = 0; p < 4; ++p) {
                        uint32_t ch = 0, cl = 0, sh = 0, sl = 0;
                        #pragma unroll
                        for (int e = 0; e < 4; ++e) {
                            int c13 = __float2int_rn(c0);
                            int s13 = __float2int_rn(s0);
                            int chh = (c13 + 64) >> 7;
                            int cll = c13 - (chh << 7);
                            int shh = (s13 + 64) >> 7;
                            int sll = s13 - (shh << 7);
                            ch |= (uint32_t)(chh & 0xFF) << (8 * e);
                            cl |= (uint32_t)(cll & 0xFF) << (8 * e);
                            sh |= (uint32_t)(shh & 0xFF) << (8 * e);
                            sl |= (uint32_t)(sll & 0xFF) << (8 * e);
                            float cn = c0 * C - s0 * S;
                            float sn = s0 * C + c0 * S;
                            c0 = cn; s0 = sn;
                        }
                        wch[p] = ch; wcl[p] = cl; wsh[p] = sh; wsl[p] = sl;
                    }
                    *(uint4*)(pch + w * 16) = make_uint4(wch[0], wch[1], wch[2], wch[3]);
                    *(uint4*)(pcl + w * 16) = make_uint4(wcl[0], wcl[1], wcl[2], wcl[3]);
                    *(uint4*)(psh + w * 16) = make_uint4(wsh[0], wsh[1], wsh[2], wsh[3]);
                    *(uint4*)(psl + w * 16) = make_uint4(wsl[0], wsl[1], wsl[2], wsl[3]);
                }
            }

            asm volatile("cp.async.wait_group 0;" ::: "memory");
            MBAR_ARRIVE(barb + s * 8);
            if (++s == NSTAGE) { s = 0; pe ^= 1; }
        }
    }
}

// ============================================================================
// Launch
// ============================================================================
extern "C" void kernel_launch(void* const* d_in, const int* in_sizes, int n_in,
                              void* d_out, int out_size) {
    const float* x    = (const float*)d_in[0];
    const float* cf   = (const float*)d_in[1];
    const float* bias = (const float*)d_in[2];
    float* out = (float*)d_out;

    cudaFuncSetAttribute(fourier_gemm,
                         cudaFuncAttributeMaxDynamicSharedMemorySize, SMEM_BYTES);

    prep_kernel<<<(OUTDIM * KDIM + 255) / 256, 256>>>(cf);
    fourier_gemm<<<MTILES * NTILES, NTHREADS, SMEM_BYTES>>>(x, bias, out);
    (void)in_sizes; (void)n_in; (void)out_size;
}

// round 12
// speedup vs baseline: 3.9013x; 3.9013x over previous
#include <cuda_runtime.h>
#include <cuda_fp16.h>
#include <cstdint>

// ============================================================================
// Problem constants
// ============================================================================
#define BATCH    4096
#define INPUTDIM 256
#define OUTDIM   256
#define GRIDSZ   64
#define KDIM     32768            // k = cs*16384 + i*64 + g
#define NPAIR    256              // loop over i; pair = (cos chunk i, sin chunk i)
#define MTILE    128
#define NTILE    64
#define MTILES   (BATCH / MTILE)  // 32
#define NTILES   (OUTDIM / NTILE) // 4
#define NTHREADS 384
#define NCONS    256              // consumer threads (warps 0-7)
#define NPROD    128              // producer threads (warps 8-11)

// SMEM stage (fp16): A buffers cosH,cosL,sinH,sinL (128 rows x 128B content),
// B buffers cos,sin (64 rows x 128B content); rows padded to 144 B
// (144 % 16 == 0 for STS.128/cp.async; r*144 mod 128 = r*16 -> conflict-free)
#define ROWB     144
#define ABUF     (128 * ROWB)     // 18432
#define BBUF     (64 * ROWB)      // 9216
#define OFF_B0   (4 * ABUF)       // 73728
#define STAGEB   (4 * ABUF + 2 * BBUF)   // 92160
#define NSTAGE   2
#define SM_BAR   (NSTAGE * STAGEB)       // 184320
#define SMEM_BYTES (SM_BAR + 64)

// ============================================================================
// Scratch (device globals — no allocation allowed)
// ============================================================================
__device__ __half g_Bf16[(size_t)OUTDIM * KDIM];   // B as fp16, K-major

// ============================================================================
// Helpers
// ============================================================================
__device__ __forceinline__ uint32_t smem_to_u32(const void* p) {
    uint32_t a;
    asm("{ .reg .u64 t; cvta.to.shared.u64 t, %1; cvt.u32.u64 %0, t; }"
        : "=r"(a) : "l"(p));
    return a;
}

__device__ __forceinline__ void cp_async16(uint32_t dst, const void* src) {
    asm volatile("cp.async.cg.shared.global [%0], [%1], 16;"
                 :: "r"(dst), "l"(src) : "memory");
}

__device__ __forceinline__ void ldsm_x4(uint32_t r[4], uint32_t addr) {
    asm volatile("ldmatrix.sync.aligned.m8n8.x4.shared.b16 {%0,%1,%2,%3}, [%4];"
                 : "=r"(r[0]), "=r"(r[1]), "=r"(r[2]), "=r"(r[3]) : "r"(addr));
}

// fp16 MMA m16n8k16, fp32 accumulate
__device__ __forceinline__ void hmma16816(float acc[4], const uint32_t a[4],
                                          uint32_t b0, uint32_t b1) {
    asm volatile(
        "mma.sync.aligned.m16n8k16.row.col.f32.f16.f16.f32 "
        "{%0,%1,%2,%3}, {%4,%5,%6,%7}, {%8,%9}, {%0,%1,%2,%3};"
        : "+f"(acc[0]), "+f"(acc[1]), "+f"(acc[2]), "+f"(acc[3])
        : "r"(a[0]), "r"(a[1]), "r"(a[2]), "r"(a[3]), "r"(b0), "r"(b1));
}

#define MBAR_INIT(addr, cnt) \
    asm volatile("mbarrier.init.shared.b64 [%0], %1;" \
                 :: "r"((uint32_t)(addr)), "r"((uint32_t)(cnt)) : "memory")

#define MBAR_ARRIVE(addr) \
    asm volatile("mbarrier.arrive.shared.b64 _, [%0];" \
                 :: "r"((uint32_t)(addr)) : "memory")

#define MBAR_WAIT(addr, parity) do { \
    uint32_t _m = (uint32_t)(addr), _p = (uint32_t)(parity), _d; \
    asm volatile( \
        "{\n\t.reg .pred p;\n\t" \
        "mbarrier.try_wait.parity.acquire.cta.shared::cta.b64 p, [%1], %2;\n\t" \
        "selp.b32 %0, 1, 0, p;\n\t}" \
        : "=r"(_d) : "r"(_m), "r"(_p) : "memory"); \
    if (!_d) { \
        asm volatile( \
            "{\n\t.reg .pred P1;\n\t" \
            "WL_%=:\n\t" \
            "mbarrier.try_wait.parity.acquire.cta.shared::cta.b64 P1, [%0], %1, 0x989680;\n\t" \
            "@P1 bra.uni WD_%=;\n\t" \
            "bra.uni WL_%=;\n\t" \
            "WD_%=:\n\t}" \
            :: "r"(_m), "r"(_p) : "memory"); \
    } \
} while (0)

// ============================================================================
// Kernel 1: prep — fouriercoeffs f32 -> K-major fp16
// ============================================================================
__global__ void prep_kernel(const float* __restrict__ cf) {
    size_t idx = (size_t)blockIdx.x * 256 + threadIdx.x;
    if (idx >= (size_t)OUTDIM * KDIM) return;
    int o = (int)(idx >> 15);            // KDIM = 2^15
    int k = (int)(idx & (KDIM - 1));
    int cs = k >> 14;
    int i  = (k >> 6) & (INPUTDIM - 1);
    int g  = k & (GRIDSZ - 1);
    float v = cf[(((size_t)cs * OUTDIM + o) * INPUTDIM + i) * GRIDSZ + g];
    g_Bf16[idx] = __float2half_rn(v);
}

// ============================================================================
// Kernel 2: warp-specialized fused fp16 GEMM (2 products: Ah*B + Al*B)
//   128 CTAs (32 M x 4 N), 384 threads:
//     warps 0-7  : consumers — warp (wm2, wn2, wq): 64(M) x 32(N) tile of the
//                  cos (wq=0) or sin (wq=1) half; shared f32 accumulator for
//                  both products; SMSP = wid&3 holds both q-variants
//     warps 8-11 : producers — thread=row, 64-step rotation, fp16 hi/lo split,
//                  packed STS.128; B fp16 via cp.async
//   2-stage mbarrier ring (proven R11 protocol: producer phase init 1).
// ============================================================================
__global__ void __launch_bounds__(NTHREADS, 1)
fourier_gemm(const float* __restrict__ x, const float* __restrict__ bias,
             float* __restrict__ out) {
    extern __shared__ char smem[];
    const uint32_t su32 = smem_to_u32(smem);
    const int tid = threadIdx.x;
    const int lid = tid & 31, wid = tid >> 5;
    const int mtile = blockIdx.x & (MTILES - 1);
    const int ntile = blockIdx.x >> 5;

    // barriers: full[0..1] at SM_BAR, empty[0..1] at SM_BAR+16
    const uint32_t barb = su32 + SM_BAR;
    if (tid == 0) {
        #pragma unroll
        for (int s = 0; s < NSTAGE; ++s) {
            MBAR_INIT(barb + s * 8,      NPROD);   // full
            MBAR_INIT(barb + 16 + s * 8, NCONS);   // empty
        }
    }
    __syncthreads();

    if (tid < NCONS) {
        // ==================== CONSUMER (warps 0-7) ====================
        const int wm2 = wid & 1;                  // M 64-row half
        const int wn2 = (wid >> 1) & 1;           // N 32-col half
        const int wq  = wid >> 2;                 // 0 = cos, 1 = sin
        const int mat = lid >> 3, mr = lid & 7;
        // A frag base (per mt add mt*16*ROWB; per ks add ks*32):
        const uint32_t a_off =
            (uint32_t)((wm2 * 64 + (mat & 1) * 8 + mr) * ROWB + (mat >> 1) * 16);
        // B frag base (per ng add ng*16*ROWB; per ks add ks*32):
        const uint32_t b_off =
            (uint32_t)((wn2 * 32 + (mat >> 1) * 8 + mr) * ROWB + (mat & 1) * 16);

        const uint32_t offAH = wq ? (2 * ABUF) : 0;
        const uint32_t offB  = OFF_B0 + wq * BBUF;

        float acc[4][4][4];
        #pragma unroll
        for (int mt = 0; mt < 4; ++mt)
            #pragma unroll
            for (int nt = 0; nt < 4; ++nt)
                #pragma unroll
                for (int q = 0; q < 4; ++q) acc[mt][nt][q] = 0.f;

        int s = 0, pf = 0;
        for (int it = 0; it < NPAIR; ++it) {
            MBAR_WAIT(barb + s * 8, pf);
            const uint32_t sbase = su32 + s * STAGEB;
            const uint32_t aHi = sbase + offAH + a_off;
            const uint32_t aLo = aHi + ABUF;
            const uint32_t bB  = sbase + offB + b_off;

            #pragma unroll
            for (int ks = 0; ks < 4; ++ks) {
                const uint32_t ko = ks * 32;
                uint32_t Ah[4][4], Al[4][4], Bf[2][4];
                #pragma unroll
                for (int mt = 0; mt < 4; ++mt)
                    ldsm_x4(Ah[mt], aHi + mt * 16 * ROWB + ko);
                #pragma unroll
                for (int ng = 0; ng < 2; ++ng)
                    ldsm_x4(Bf[ng], bB + ng * 16 * ROWB + ko);
                #pragma unroll
                for (int mt = 0; mt < 4; ++mt)
                    #pragma unroll
                    for (int ng = 0; ng < 2; ++ng) {
                        hmma16816(acc[mt][ng * 2],     Ah[mt], Bf[ng][0], Bf[ng][1]);
                        hmma16816(acc[mt][ng * 2 + 1], Ah[mt], Bf[ng][2], Bf[ng][3]);
                    }
                #pragma unroll
                for (int mt = 0; mt < 4; ++mt)
                    ldsm_x4(Al[mt], aLo + mt * 16 * ROWB + ko);
                #pragma unroll
                for (int mt = 0; mt < 4; ++mt)
                    #pragma unroll
                    for (int ng = 0; ng < 2; ++ng) {
                        hmma16816(acc[mt][ng * 2],     Al[mt], Bf[ng][0], Bf[ng][1]);
                        hmma16816(acc[mt][ng * 2 + 1], Al[mt], Bf[ng][2], Bf[ng][3]);
                    }
            }
            MBAR_ARRIVE(barb + 16 + s * 8);
            if (++s == NSTAGE) { s = 0; pf ^= 1; }
        }

        // ---- epilogue: merge cos(q=0) + sin(q=1) via smem scratch ----
        // Barrier BEFORE writes: all consumers must finish stage reads first.
        asm volatile("bar.sync 1, %0;" :: "n"(NCONS) : "memory");
        {
            const int fl = (wn2 * 2 + wm2) * 32 + lid;     // 0..127
            float* scr = (float*)(smem) + (size_t)fl * 68; // 68-float stride
            if (wq == 1) {
                #pragma unroll
                for (int mt = 0; mt < 4; ++mt)
                    #pragma unroll
                    for (int nt = 0; nt < 4; ++nt)
                        *(float4*)(scr + (mt * 4 + nt) * 4) =
                            make_float4(acc[mt][nt][0], acc[mt][nt][1],
                                        acc[mt][nt][2], acc[mt][nt][3]);
            }
            asm volatile("bar.sync 1, %0;" :: "n"(NCONS) : "memory");
            if (wq == 0) {
                #pragma unroll
                for (int mt = 0; mt < 4; ++mt) {
                    int r0 = mtile * MTILE + wm2 * 64 + mt * 16 + (lid >> 2);
                    #pragma unroll
                    for (int nt = 0; nt < 4; ++nt) {
                        float4 o2 = *(float4*)(scr + (mt * 4 + nt) * 4);
                        int c0 = ntile * NTILE + wn2 * 32 + nt * 8 + (lid & 3) * 2;
                        float b0 = __ldg(bias + c0);
                        float b1 = __ldg(bias + c0 + 1);
                        *(float2*)(out + (size_t)r0 * OUTDIM + c0) =
                            make_float2(acc[mt][nt][0] + o2.x + b0,
                                        acc[mt][nt][1] + o2.y + b1);
                        *(float2*)(out + (size_t)(r0 + 8) * OUTDIM + c0) =
                            make_float2(acc[mt][nt][2] + o2.z + b0,
                                        acc[mt][nt][3] + o2.w + b1);
                    }
                }
            }
        }
    } else {
        // ==================== PRODUCER (warps 8-11) ====================
        const int ptid = tid - NCONS;               // 0..127 == row
        const int fb = ptid;
        const float* xrow = x + (size_t)(mtile * MTILE + fb) * INPUTDIM;
        const char* bfp = (const char*)g_Bf16;

        int s = 0, pe = 1;                          // phase init 1 (R11 proven)
        for (int it = 0; it < NPAIR; ++it) {
            MBAR_WAIT(barb + 16 + s * 8, pe);
            const uint32_t sbase = su32 + s * STAGEB;

            // ---- B tiles: 2 buffers (cos, sin), 16 KB ----
            #pragma unroll
            for (int q = 0; q < 8; ++q) {
                int idx = ptid + q * NPROD;          // 0..1023 segs of 16B
                int buf = idx >> 9;                  // 0..1 (= cs)
                int r   = (idx >> 3) & 63;
                int seg = idx & 7;
                uint32_t dst = sbase + OFF_B0 + buf * BBUF + r * ROWB + seg * 16;
                const char* src = bfp
                    + (size_t)(ntile * NTILE + r) * (KDIM * 2)
                    + (size_t)buf * 32768 + (size_t)it * 128 + seg * 16;
                cp_async16(dst, src);
            }
            asm volatile("cp.async.commit_group;" ::: "memory");

            // ---- A: 64-step rotation, fp16 hi/lo split, STS.128 ----
            {
                float xv = __ldg(xrow + it);
                float S, C;
                sincosf(xv, &S, &C);
                float c0 = C, s0 = S;               // freq 1

                char* pch = smem + s * STAGEB + fb * ROWB;            // cos hi
                char* pcl = pch + ABUF;                               // cos lo
                char* psh = pch + 2 * ABUF;                           // sin hi
                char* psl = pch + 3 * ABUF;                           // sin lo

                #pragma unroll
                for (int w = 0; w < 8; ++w) {
                    uint32_t wch[4], wcl[4], wsh[4], wsl[4];
                    #pragma unroll
                    for (int p = 0; p < 4; ++p) {
                        float vc0 = c0, vs0 = s0;
                        float c1 = c0 * C - s0 * S;
                        float s1 = s0 * C + c0 * S;
                        float vc1 = c1, vs1 = s1;
                        c0 = c1 * C - s1 * S;
                        s0 = s1 * C + c1 * S;

                        __half hc0 = __float2half_rn(vc0);
                        __half hc1 = __float2half_rn(vc1);
                        __half2 hcp = __halves2half2(hc0, hc1);
                        wch[p] = *(uint32_t*)&hcp;
                        __half2 lcp = __floats2half2_rn(
                            vc0 - __half2float(hc0), vc1 - __half2float(hc1));
                        wcl[p] = *(uint32_t*)&lcp;

                        __half hs0 = __float2half_rn(vs0);
                        __half hs1 = __float2half_rn(vs1);
                        __half2 hsp = __halves2half2(hs0, hs1);
                        wsh[p] = *(uint32_t*)&hsp;
                        __half2 lsp = __floats2half2_rn(
                            vs0 - __half2float(hs0), vs1 - __half2float(hs1));
                        wsl[p] = *(uint32_t*)&lsp;
                    }
                    *(uint4*)(pch + w * 16) = make_uint4(wch[0], wch[1], wch[2], wch[3]);
                    *(uint4*)(pcl + w * 16) = make_uint4(wcl[0], wcl[1], wcl[2], wcl[3]);
                    *(uint4*)(psh + w * 16) = make_uint4(wsh[0], wsh[1], wsh[2], wsh[3]);
                    *(uint4*)(psl + w * 16) = make_uint4(wsl[0], wsl[1], wsl[2], wsl[3]);
                }
            }

            asm volatile("cp.async.wait_group 0;" ::: "memory");
            MBAR_ARRIVE(barb + s * 8);
            if (++s == NSTAGE) { s = 0; pe ^= 1; }
        }
    }
}

// ============================================================================
// Launch
// ============================================================================
extern "C" void kernel_launch(void* const* d_in, const int* in_sizes, int n_in,
                              void* d_out, int out_size) {
    const float* x    = (const float*)d_in[0];
    const float* cf   = (const float*)d_in[1];
    const float* bias = (const float*)d_in[2];
    float* out = (float*)d_out;

    cudaFuncSetAttribute(fourier_gemm,
                         cudaFuncAttributeMaxDynamicSharedMemorySize, SMEM_BYTES);

    prep_kernel<<<(OUTDIM * KDIM + 255) / 256, 256>>>(cf);
    fourier_gemm<<<MTILES * NTILES, NTHREADS, SMEM_BYTES>>>(x, bias, out);
    (void)in_sizes; (void)n_in; (void)out_size;
}

// round 13
// speedup vs baseline: 7.0941x; 1.8184x over previous
#include <cuda_runtime.h>
#include <cuda_fp16.h>
#include <cstdint>

// ============================================================================
// Problem constants
// ============================================================================
#define BATCH    4096
#define INPUTDIM 256
#define OUTDIM   256
#define GRIDSZ   64
#define KDIM     32768            // k = cs*16384 + i*64 + g
#define NPAIR    256              // loop over i; pair = (cos chunk i, sin chunk i)
#define MTILE    128
#define NTILE    64
#define MTILES   (BATCH / MTILE)  // 32
#define NTILES   (OUTDIM / NTILE) // 4
#define NTHREADS 384
#define NCONS    256              // consumer threads (warps 0-7)
#define NPROD    128              // producer threads (warps 8-11)

// SMEM stage (fp16, single product): A buffers cos,sin (128 rows x 128B),
// B buffers cos,sin (64 rows x 128B); rows padded to 144 B
// (144 % 16 == 0 for STS.128/cp.async; r*144 mod 128 = r*16 -> conflict-free)
#define ROWB     144
#define ABUF     (128 * ROWB)     // 18432
#define BBUF     (64 * ROWB)      // 9216
#define OFF_B0   (2 * ABUF)       // 36864
#define STAGEB   (2 * ABUF + 2 * BBUF)   // 55296
#define NSTAGE   3
#define SM_BAR   (NSTAGE * STAGEB)       // 165888
#define SMEM_BYTES (SM_BAR + 64)

// ============================================================================
// Scratch (device globals — no allocation allowed)
// ============================================================================
__device__ __half g_Bf16[(size_t)OUTDIM * KDIM];   // B as fp16, K-major

// ============================================================================
// Helpers
// ============================================================================
__device__ __forceinline__ uint32_t smem_to_u32(const void* p) {
    uint32_t a;
    asm("{ .reg .u64 t; cvta.to.shared.u64 t, %1; cvt.u32.u64 %0, t; }"
        : "=r"(a) : "l"(p));
    return a;
}

__device__ __forceinline__ void cp_async16(uint32_t dst, const void* src) {
    asm volatile("cp.async.cg.shared.global [%0], [%1], 16;"
                 :: "r"(dst), "l"(src) : "memory");
}

__device__ __forceinline__ void ldsm_x4(uint32_t r[4], uint32_t addr) {
    asm volatile("ldmatrix.sync.aligned.m8n8.x4.shared.b16 {%0,%1,%2,%3}, [%4];"
                 : "=r"(r[0]), "=r"(r[1]), "=r"(r[2]), "=r"(r[3]) : "r"(addr));
}

// fp16 MMA m16n8k16, fp32 accumulate
__device__ __forceinline__ void hmma16816(float acc[4], const uint32_t a[4],
                                          uint32_t b0, uint32_t b1) {
    asm volatile(
        "mma.sync.aligned.m16n8k16.row.col.f32.f16.f16.f32 "
        "{%0,%1,%2,%3}, {%4,%5,%6,%7}, {%8,%9}, {%0,%1,%2,%3};"
        : "+f"(acc[0]), "+f"(acc[1]), "+f"(acc[2]), "+f"(acc[3])
        : "r"(a[0]), "r"(a[1]), "r"(a[2]), "r"(a[3]), "r"(b0), "r"(b1));
}

#define MBAR_INIT(addr, cnt) \
    asm volatile("mbarrier.init.shared.b64 [%0], %1;" \
                 :: "r"((uint32_t)(addr)), "r"((uint32_t)(cnt)) : "memory")

#define MBAR_ARRIVE(addr) \
    asm volatile("mbarrier.arrive.shared.b64 _, [%0];" \
                 :: "r"((uint32_t)(addr)) : "memory")

#define MBAR_WAIT(addr, parity) do { \
    uint32_t _m = (uint32_t)(addr), _p = (uint32_t)(parity), _d; \
    asm volatile( \
        "{\n\t.reg .pred p;\n\t" \
        "mbarrier.try_wait.parity.acquire.cta.shared::cta.b64 p, [%1], %2;\n\t" \
        "selp.b32 %0, 1, 0, p;\n\t}" \
        : "=r"(_d) : "r"(_m), "r"(_p) : "memory"); \
    if (!_d) { \
        asm volatile( \
            "{\n\t.reg .pred P1;\n\t" \
            "WL_%=:\n\t" \
            "mbarrier.try_wait.parity.acquire.cta.shared::cta.b64 P1, [%0], %1, 0x989680;\n\t" \
            "@P1 bra.uni WD_%=;\n\t" \
            "bra.uni WL_%=;\n\t" \
            "WD_%=:\n\t}" \
            :: "r"(_m), "r"(_p) : "memory"); \
    } \
} while (0)

// ============================================================================
// Kernel 1: prep — fouriercoeffs f32 -> K-major fp16
// ============================================================================
__global__ void prep_kernel(const float* __restrict__ cf) {
    size_t idx = (size_t)blockIdx.x * 256 + threadIdx.x;
    if (idx >= (size_t)OUTDIM * KDIM) return;
    int o = (int)(idx >> 15);            // KDIM = 2^15
    int k = (int)(idx & (KDIM - 1));
    int cs = k >> 14;
    int i  = (k >> 6) & (INPUTDIM - 1);
    int g  = k & (GRIDSZ - 1);
    float v = cf[(((size_t)cs * OUTDIM + o) * INPUTDIM + i) * GRIDSZ + g];
    g_Bf16[idx] = __float2half_rn(v);
}

// ============================================================================
// Kernel 2: warp-specialized fused fp16 GEMM — SINGLE product (A16 x B16)
//   128 CTAs (32 M x 4 N), 384 threads:
//     warps 0-7  : consumers — warp (wm2, wn2, wq): 64(M) x 32(N) tile of the
//                  cos (wq=0) or sin (wq=1) half
//     warps 8-11 : producers — thread=row, 64-step rotation, fp16 pack,
//                  STS.128; B fp16 via cp.async
//   3-stage mbarrier ring (proven protocol: producer phase init 1).
// ============================================================================
__global__ void __launch_bounds__(NTHREADS, 1)
fourier_gemm(const float* __restrict__ x, const float* __restrict__ bias,
             float* __restrict__ out) {
    extern __shared__ char smem[];
    const uint32_t su32 = smem_to_u32(smem);
    const int tid = threadIdx.x;
    const int lid = tid & 31, wid = tid >> 5;
    const int mtile = blockIdx.x & (MTILES - 1);
    const int ntile = blockIdx.x >> 5;

    // barriers: full[0..2] at SM_BAR, empty[0..2] at SM_BAR+24
    const uint32_t barb = su32 + SM_BAR;
    if (tid == 0) {
        #pragma unroll
        for (int s = 0; s < NSTAGE; ++s) {
            MBAR_INIT(barb + s * 8,      NPROD);   // full
            MBAR_INIT(barb + 24 + s * 8, NCONS);   // empty
        }
    }
    __syncthreads();

    if (tid < NCONS) {
        // ==================== CONSUMER (warps 0-7) ====================
        const int wm2 = wid & 1;                  // M 64-row half
        const int wn2 = (wid >> 1) & 1;           // N 32-col half
        const int wq  = wid >> 2;                 // 0 = cos, 1 = sin
        const int mat = lid >> 3, mr = lid & 7;
        const uint32_t a_off =
            (uint32_t)((wm2 * 64 + (mat & 1) * 8 + mr) * ROWB + (mat >> 1) * 16);
        const uint32_t b_off =
            (uint32_t)((wn2 * 32 + (mat >> 1) * 8 + mr) * ROWB + (mat & 1) * 16);

        const uint32_t offA = wq ? ABUF : 0;
        const uint32_t offB = OFF_B0 + wq * BBUF;

        float acc[4][4][4];
        #pragma unroll
        for (int mt = 0; mt < 4; ++mt)
            #pragma unroll
            for (int nt = 0; nt < 4; ++nt)
                #pragma unroll
                for (int q = 0; q < 4; ++q) acc[mt][nt][q] = 0.f;

        int s = 0, pf = 0;
        for (int it = 0; it < NPAIR; ++it) {
            MBAR_WAIT(barb + s * 8, pf);
            const uint32_t sbase = su32 + s * STAGEB;
            const uint32_t aB = sbase + offA + a_off;
            const uint32_t bB = sbase + offB + b_off;

            #pragma unroll
            for (int ks = 0; ks < 4; ++ks) {
                const uint32_t ko = ks * 32;
                uint32_t Af[4][4], Bf[2][4];
                #pragma unroll
                for (int mt = 0; mt < 4; ++mt)
                    ldsm_x4(Af[mt], aB + mt * 16 * ROWB + ko);
                #pragma unroll
                for (int ng = 0; ng < 2; ++ng)
                    ldsm_x4(Bf[ng], bB + ng * 16 * ROWB + ko);
                #pragma unroll
                for (int mt = 0; mt < 4; ++mt)
                    #pragma unroll
                    for (int ng = 0; ng < 2; ++ng) {
                        hmma16816(acc[mt][ng * 2],     Af[mt], Bf[ng][0], Bf[ng][1]);
                        hmma16816(acc[mt][ng * 2 + 1], Af[mt], Bf[ng][2], Bf[ng][3]);
                    }
            }
            MBAR_ARRIVE(barb + 24 + s * 8);
            if (++s == NSTAGE) { s = 0; pf ^= 1; }
        }

        // ---- epilogue: merge cos(q=0) + sin(q=1) via smem scratch ----
        asm volatile("bar.sync 1, %0;" :: "n"(NCONS) : "memory");
        {
            const int fl = (wn2 * 2 + wm2) * 32 + lid;     // 0..127
            float* scr = (float*)(smem) + (size_t)fl * 68; // 68-float stride
            if (wq == 1) {
                #pragma unroll
                for (int mt = 0; mt < 4; ++mt)
                    #pragma unroll
                    for (int nt = 0; nt < 4; ++nt)
                        *(float4*)(scr + (mt * 4 + nt) * 4) =
                            make_float4(acc[mt][nt][0], acc[mt][nt][1],
                                        acc[mt][nt][2], acc[mt][nt][3]);
            }
            asm volatile("bar.sync 1, %0;" :: "n"(NCONS) : "memory");
            if (wq == 0) {
                #pragma unroll
                for (int mt = 0; mt < 4; ++mt) {
                    int r0 = mtile * MTILE + wm2 * 64 + mt * 16 + (lid >> 2);
                    #pragma unroll
                    for (int nt = 0; nt < 4; ++nt) {
                        float4 o2 = *(float4*)(scr + (mt * 4 + nt) * 4);
                        int c0 = ntile * NTILE + wn2 * 32 + nt * 8 + (lid & 3) * 2;
                        float b0 = __ldg(bias + c0);
                        float b1 = __ldg(bias + c0 + 1);
                        *(float2*)(out + (size_t)r0 * OUTDIM + c0) =
                            make_float2(acc[mt][nt][0] + o2.x + b0,
                                        acc[mt][nt][1] + o2.y + b1);
                        *(float2*)(out + (size_t)(r0 + 8) * OUTDIM + c0) =
                            make_float2(acc[mt][nt][2] + o2.z + b0,
                                        acc[mt][nt][3] + o2.w + b1);
                    }
                }
            }
        }
    } else {
        // ==================== PRODUCER (warps 8-11) ====================
        const int ptid = tid - NCONS;               // 0..127 == row
        const int fb = ptid;
        const float* xrow = x + (size_t)(mtile * MTILE + fb) * INPUTDIM;
        const char* bfp = (const char*)g_Bf16;

        int s = 0, pe = 1;                          // phase init 1 (proven)
        for (int it = 0; it < NPAIR; ++it) {
            MBAR_WAIT(barb + 24 + s * 8, pe);
            const uint32_t sbase = su32 + s * STAGEB;

            // ---- B tiles: 2 buffers (cos, sin), 16 KB ----
            #pragma unroll
            for (int q = 0; q < 8; ++q) {
                int idx = ptid + q * NPROD;          // 0..1023 segs of 16B
                int buf = idx >> 9;                  // 0..1 (= cs)
                int r   = (idx >> 3) & 63;
                int seg = idx & 7;
                uint32_t dst = sbase + OFF_B0 + buf * BBUF + r * ROWB + seg * 16;
                const char* src = bfp
                    + (size_t)(ntile * NTILE + r) * (KDIM * 2)
                    + (size_t)buf * 32768 + (size_t)it * 128 + seg * 16;
                cp_async16(dst, src);
            }
            asm volatile("cp.async.commit_group;" ::: "memory");

            // ---- A: 64-step rotation, fp16 pack, STS.128 (no lo split) ----
            {
                float xv = __ldg(xrow + it);
                float S, C;
                sincosf(xv, &S, &C);
                float c0 = C, s0 = S;               // freq 1

                char* pc = smem + s * STAGEB + fb * ROWB;   // cos
                char* ps = pc + ABUF;                       // sin

                #pragma unroll
                for (int w = 0; w < 8; ++w) {
                    uint32_t wc[4], ws[4];
                    #pragma unroll
                    for (int p = 0; p < 4; ++p) {
                        float vc0 = c0, vs0 = s0;
                        float c1 = c0 * C - s0 * S;
                        float s1 = s0 * C + c0 * S;
                        float vc1 = c1, vs1 = s1;
                        c0 = c1 * C - s1 * S;
                        s0 = s1 * C + c1 * S;

                        __half2 hc = __floats2half2_rn(vc0, vc1);
                        __half2 hs = __floats2half2_rn(vs0, vs1);
                        wc[p] = *(uint32_t*)&hc;
                        ws[p] = *(uint32_t*)&hs;
                    }
                    *(uint4*)(pc + w * 16) = make_uint4(wc[0], wc[1], wc[2], wc[3]);
                    *(uint4*)(ps + w * 16) = make_uint4(ws[0], ws[1], ws[2], ws[3]);
                }
            }

            asm volatile("cp.async.wait_group 0;" ::: "memory");
            MBAR_ARRIVE(barb + s * 8);
            if (++s == NSTAGE) { s = 0; pe ^= 1; }
        }
    }
}

// ============================================================================
// Launch
// ============================================================================
extern "C" void kernel_launch(void* const* d_in, const int* in_sizes, int n_in,
                              void* d_out, int out_size) {
    const float* x    = (const float*)d_in[0];
    const float* cf   = (const float*)d_in[1];
    const float* bias = (const float*)d_in[2];
    float* out = (float*)d_out;

    cudaFuncSetAttribute(fourier_gemm,
                         cudaFuncAttributeMaxDynamicSharedMemorySize, SMEM_BYTES);

    prep_kernel<<<(OUTDIM * KDIM + 255) / 256, 256>>>(cf);
    fourier_gemm<<<MTILES * NTILES, NTHREADS, SMEM_BYTES>>>(x, bias, out);
    (void)in_sizes; (void)n_in; (void)out_size;
}